// round 15
// baseline (speedup 1.0000x reference)
#include <cuda_runtime.h>
#include <cstdint>

constexpr int BATCH = 128;
constexpr int NODES = 8192;
constexpr int NI    = 6;
constexpr int NE    = 64;
constexpr int BB    = 16;     // batches per thread
constexpr int TPB   = 64;     // 1024 CTAs -> near-perfect SM balance (6.92/SM)
constexpr int PF    = 4;      // x prefetch depth (register ring, slot = bb&3)
constexpr int XSTRIDE = NODES * NI;   // floats between consecutive batches

using u64 = unsigned long long;

__device__ __forceinline__ u64 pk2(float lo, float hi) {
    u64 r; asm("mov.b64 %0, {%1, %2};" : "=l"(r) : "f"(lo), "f"(hi)); return r;
}
__device__ __forceinline__ void upk2(u64 v, float& lo, float& hi) {
    asm("mov.b64 {%0, %1}, %2;" : "=f"(lo), "=f"(hi) : "l"(v));
}
__device__ __forceinline__ u64 fma2(u64 a, u64 b, u64 c) {
    u64 d; asm("fma.rn.f32x2 %0, %1, %2, %3;" : "=l"(d) : "l"(a), "l"(b), "l"(c)); return d;
}
__device__ __forceinline__ u64 sub2(u64 a, u64 b) {
    u64 d; asm("sub.rn.f32x2 %0, %1, %2;" : "=l"(d) : "l"(a), "l"(b)); return d;
}

// out[b,n] = 6-D multilinear interp of tables[n,:] at clip(x[b,n,:], 0, 1).
// Bits 0,1 folded into per-node quad coefficients (a + x0 b + x1 c + x0x1 d),
// bits 2..4 packed difference-form lerps, bit 5 packed across f32x2 lanes.
// R15: TPB=64 -> 1024 CTAs, occ 8 (same 16 warps/SM) but SM imbalance drops
// from 15.6% (3-vs-4 CTAs) to 1.2% (7-vs-6.92). PF=4 register ring doubles
// x lookahead (~400cyc) against ~600cyc DRAM latency.
__global__ void __launch_bounds__(TPB, 8)
lut_kernel(const float* __restrict__ x,
           const float* __restrict__ tables,
           float* __restrict__ out)
{
    __shared__ float tbl[TPB * NE];          // 16 KB static

    const int tid = threadIdx.x;
    const int n0  = blockIdx.x * TPB;        // first node of this block
    const int b0  = blockIdx.y * BB;         // first batch of this block

    const float* xt = x + ((size_t)b0 * NODES + n0 + tid) * NI;

    // ---- kick off x prefetch for batches 0..PF-1 FIRST (overlaps table stage) ----
    float2 buf[PF][3];
    #pragma unroll
    for (int s = 0; s < PF; s++) {
        const float* p = xt + (size_t)s * XSTRIDE;
        buf[s][0] = *(const float2*)(p + 0);
        buf[s][1] = *(const float2*)(p + 2);
        buf[s][2] = *(const float2*)(p + 4);
    }

    // ---- stage this block's 16KB table chunk: coalesced LDG -> +2*row-rotated STS.64 ----
    {
        const float4* tg = (const float4*)(tables + (size_t)n0 * NE);
        #pragma unroll
        for (int j = 0; j < (TPB * NE / 4) / TPB; j++) {    // 16 float4 per thread
            int i = tid + j * TPB;                          // coalesced gmem index
            float4 v = tg[i];
            int r  = i >> 4;                                // dest row
            int c0 = (i & 15) * 4;                          // first word (even)
            float* row = tbl + r * NE;
            int w0 = (c0     + 2 * r) & (NE - 1);           // even -> 8B aligned
            int w1 = (c0 + 2 + 2 * r) & (NE - 1);
            *(float2*)(row + w0) = make_float2(v.x, v.y);
            *(float2*)(row + w1) = make_float2(v.z, v.w);
        }
    }
    __syncthreads();

    // ---- per-node packed quad coefficients over bits 0,1 (pairing = bit 5) ----
    // quad m covers entries 4m..4m+3 (lane lo) and 4m+32..4m+35 (lane hi):
    //   val = a + x0*b + x1*c + x0*x1*d
    u64 Aq[8], Bq[8], Cq[8], Dq[8];
    {
        const float* tr = tbl + (size_t)tid * NE;
        const int rot = (2 * tid) & (NE - 1);               // even: float2 pairs intact
        #pragma unroll
        for (int m = 0; m < 8; m++) {
            float2 l01 = *(const float2*)(tr + ((4*m      + rot) & (NE - 1)));
            float2 l23 = *(const float2*)(tr + ((4*m + 2  + rot) & (NE - 1)));
            float2 h01 = *(const float2*)(tr + ((4*m + 32 + rot) & (NE - 1)));
            float2 h23 = *(const float2*)(tr + ((4*m + 34 + rot) & (NE - 1)));
            float lb = l01.y - l01.x, hb = h01.y - h01.x;
            Aq[m] = pk2(l01.x, h01.x);
            Bq[m] = pk2(lb, hb);
            Cq[m] = pk2(l23.x - l01.x, h23.x - h01.x);
            Dq[m] = pk2((l23.y - l23.x) - lb, (h23.y - h23.x) - hb);
        }
    }

    // ---- fold body (shared by mainloop and epilogue) ----
    auto fold = [&](float2 q0, float2 q1, float2 q2) -> float {
        float c0 = __saturatef(q0.x), c1 = __saturatef(q0.y);
        float c2 = __saturatef(q1.x), c3 = __saturatef(q1.y);
        float c4 = __saturatef(q2.x), c5 = __saturatef(q2.y);
        float c01 = c0 * c1;
        u64 x0  = pk2(c0,  c0), x1 = pk2(c1, c1), x01 = pk2(c01, c01);
        u64 x2  = pk2(c2,  c2), x3 = pk2(c3, c3), x4  = pk2(c4, c4);

        u64 W[8];
        #pragma unroll
        for (int m = 0; m < 8; m++)
            W[m] = fma2(x01, Dq[m], fma2(x1, Cq[m], fma2(x0, Bq[m], Aq[m])));
        #pragma unroll
        for (int m = 0; m < 4; m++) W[m] = fma2(x2, sub2(W[2*m+1], W[2*m]), W[2*m]);
        #pragma unroll
        for (int m = 0; m < 2; m++) W[m] = fma2(x3, sub2(W[2*m+1], W[2*m]), W[2*m]);
        W[0] = fma2(x4, sub2(W[1], W[0]), W[0]);

        float lo, hi; upk2(W[0], lo, hi);
        return fmaf(c5, hi - lo, lo);
    };

    float*       op   = out + (size_t)b0 * NODES + n0 + tid;
    const float* xpre = xt + (size_t)PF * XSTRIDE;

    // ---- mainloop: 12 iters, unroll 4 (slot index bb&3 static), ptr increments ----
    #pragma unroll 4
    for (int bb = 0; bb < BB - PF; bb++) {
        const int s = bb & (PF - 1);
        float2 q0 = buf[s][0];
        float2 q1 = buf[s][1];
        float2 q2 = buf[s][2];

        buf[s][0] = *(const float2*)(xpre + 0);             // refill slot for bb+PF
        buf[s][1] = *(const float2*)(xpre + 2);
        buf[s][2] = *(const float2*)(xpre + 4);
        xpre += XSTRIDE;

        *op = fold(q0, q1, q2);
        op += NODES;
    }

    // ---- epilogue: last PF batches, no refill (slots 0..3 static) ----
    #pragma unroll
    for (int bb = BB - PF; bb < BB; bb++) {
        const int s = bb & (PF - 1);
        *op = fold(buf[s][0], buf[s][1], buf[s][2]);
        op += NODES;
    }
}

extern "C" void kernel_launch(void* const* d_in, const int* in_sizes, int n_in,
                              void* d_out, int out_size)
{
    const float* x;
    const float* tables;
    if (in_sizes[0] == BATCH * NODES * NI) {
        x = (const float*)d_in[0]; tables = (const float*)d_in[1];
    } else {
        x = (const float*)d_in[1]; tables = (const float*)d_in[0];
    }
    dim3 grid(NODES / TPB, BATCH / BB);
    lut_kernel<<<grid, TPB>>>(x, tables, (float*)d_out);
}